// round 9
// baseline (speedup 1.0000x reference)
#include <cuda_runtime.h>
#include <math.h>

// Problem constants (fixed shapes from reference)
#define BB   2
#define NN   16384        // 2^14
#define MM   4096
#define CC   64
#define KK   16
#define WPB  8            // warps per block in knn
#define NQ   (BB * MM)    // 8192 queries

// Spatial grid
#define GD     40
#define LO     (-5.0f)
#define HH     0.25f
#define NCELL  (GD * GD * GD)          // 64000
#define NCTOT  (BB * NCELL)            // 128000
#define NSB    ((NCTOT + 1023) / 1024) // 125 scan blocks

#define BIGF 1e30f
#define FULLMASK 0xffffffffu

// Scratch (__device__ globals; no allocs allowed)
__device__ float  g_xt[BB * NN * CC];   // transposed features (B,N,C), 8 MB
__device__ float4 g_spts[BB * NN];      // cell-sorted packed points (x,y,z,|p|^2)
__device__ int    g_sidx[BB * NN];      // original (within-batch) index per sorted point
__device__ int    g_pcell[BB * NN];     // cell id per original point
__device__ int    g_cnt[NCTOT];         // per-cell counts
__device__ int    g_scan[NCTOT];        // block-local exclusive scan
__device__ int    g_cellstart[NCTOT + 1];
__device__ int    g_cursor[NCTOT];
__device__ int    g_bsum[NSB];
__device__ int    g_bsumx[NSB];

__device__ __forceinline__ int cellof(float x) {
    int c = (int)floorf((x - LO) * (1.0f / HH));
    return min(GD - 1, max(0, c));
}

// ---------------------------------------------------------------------------
// Build kernels
// ---------------------------------------------------------------------------
__global__ __launch_bounds__(256) void zero_kernel() {
    const int i = blockIdx.x * 256 + threadIdx.x;
    if (i < NCTOT) g_cnt[i] = 0;
}

__global__ __launch_bounds__(256) void count_kernel(const float* __restrict__ p1) {
    const int i = blockIdx.x * 256 + threadIdx.x;   // 0 .. BB*NN-1
    const float x = p1[3 * i], y = p1[3 * i + 1], z = p1[3 * i + 2];
    const int c = (cellof(z) * GD + cellof(y)) * GD + cellof(x);
    g_pcell[i] = c;
    atomicAdd(&g_cnt[(i >> 14) * NCELL + c], 1);
}

__global__ __launch_bounds__(1024) void scan1_kernel() {
    __shared__ int ws[32];
    const int tid = threadIdx.x, lane = tid & 31, wid = tid >> 5;
    const int gid = blockIdx.x * 1024 + tid;
    const int v = (gid < NCTOT) ? g_cnt[gid] : 0;
    int x = v;
#pragma unroll
    for (int o = 1; o < 32; o <<= 1) {
        const int t = __shfl_up_sync(FULLMASK, x, o);
        if (lane >= o) x += t;
    }
    if (lane == 31) ws[wid] = x;
    __syncthreads();
    if (wid == 0) {
        const int orig = ws[lane];
        int s = orig;
#pragma unroll
        for (int o = 1; o < 32; o <<= 1) {
            const int t = __shfl_up_sync(FULLMASK, s, o);
            if (lane >= o) s += t;
        }
        ws[lane] = s - orig;   // exclusive warp offset
    }
    __syncthreads();
    const int excl = x - v + ws[wid];
    if (gid < NCTOT) g_scan[gid] = excl;
    if (tid == 1023) g_bsum[blockIdx.x] = excl + v;   // block total
}

__global__ __launch_bounds__(32) void scan2_kernel() {
    const int lane = threadIdx.x;
    int carry = 0;
    for (int base = 0; base < NSB; base += 32) {
        const int i = base + lane;
        const int v = (i < NSB) ? g_bsum[i] : 0;
        int x = v;
#pragma unroll
        for (int o = 1; o < 32; o <<= 1) {
            const int t = __shfl_up_sync(FULLMASK, x, o);
            if (lane >= o) x += t;
        }
        if (i < NSB) g_bsumx[i] = carry + x - v;
        carry += __shfl_sync(FULLMASK, x, 31);
    }
}

__global__ __launch_bounds__(256) void scan3_kernel() {
    const int gid = blockIdx.x * 256 + threadIdx.x;
    if (gid < NCTOT) {
        const int s = g_scan[gid] + g_bsumx[gid >> 10];
        g_cellstart[gid] = s;
        g_cursor[gid]    = s;
    }
    if (gid == 0) g_cellstart[NCTOT] = BB * NN;
}

__global__ __launch_bounds__(256) void scatter_kernel(const float* __restrict__ p1) {
    const int i = blockIdx.x * 256 + threadIdx.x;   // 0 .. BB*NN-1
    const float x = p1[3 * i], y = p1[3 * i + 1], z = p1[3 * i + 2];
    const int b = i >> 14;
    const int pos = atomicAdd(&g_cursor[b * NCELL + g_pcell[i]], 1);
    g_spts[pos] = make_float4(x, y, z, fmaf(x, x, fmaf(y, y, z * z)));
    g_sidx[pos] = i & (NN - 1);
}

// ---------------------------------------------------------------------------
// Feature transpose x1 (B,C,N) -> g_xt (B,N,C)
// ---------------------------------------------------------------------------
__global__ __launch_bounds__(256) void transpose_kernel(const float* __restrict__ x1) {
    __shared__ float t[32][33];
    const int b  = blockIdx.z;
    const int n0 = blockIdx.x * 32;
    const int c0 = blockIdx.y * 32;
    const int tx = threadIdx.x;
    const int ty = threadIdx.y;

    const float* src = x1  + (size_t)b * CC * NN;
    float*       dst = g_xt + (size_t)b * NN * CC;

#pragma unroll
    for (int i = 0; i < 32; i += 8)
        t[ty + i][tx] = src[(size_t)(c0 + ty + i) * NN + (n0 + tx)];
    __syncthreads();
#pragma unroll
    for (int i = 0; i < 32; i += 8)
        dst[(size_t)(n0 + ty + i) * CC + (c0 + tx)] = t[tx][ty + i];
}

// ---------------------------------------------------------------------------
// Grid-accelerated exact KNN(16) + fused feature gather/mean.
// One warp per query. Lanes 0..15 hold the global top-16 sorted ascending by
// (d', idx) — tie-stable, matching jax top_k and immune to nondeterministic
// within-cell scatter order. Shells expand in Chebyshev rings; exact stop when
// distance to the scanned box boundary exceeds the current 16th distance
// (with conservative fp margin). d' = |p|^2 - 2 q.p (order-equiv to |p-q|^2).
// ---------------------------------------------------------------------------
__global__ __launch_bounds__(32 * WPB) void knn_kernel(const float* __restrict__ p2,
                                                       float* __restrict__ out) {
    const int warp = threadIdx.x >> 5;
    const int lane = threadIdx.x & 31;
    const int q    = blockIdx.x * WPB + warp;
    const int b    = q >> 12;          // q / MM
    const int m    = q & (MM - 1);

    const float qx = p2[((size_t)b * MM + m) * 3 + 0];
    const float qy = p2[((size_t)b * MM + m) * 3 + 1];
    const float qz = p2[((size_t)b * MM + m) * 3 + 2];
    const float nqx = -2.0f * qx, nqy = -2.0f * qy, nqz = -2.0f * qz;
    const float qq  = fmaf(qx, qx, fmaf(qy, qy, qz * qz));

    const int cx = cellof(qx), cy = cellof(qy), cz = cellof(qz);
    const int cbase = b * NCELL;
    const float FINF = __int_as_float(0x7f800000);

    float topd = BIGF;          // lanes 0..15: sorted top-16
    int   topi = 0x7fffffff;
    float tau  = BIGF;          // 16th (d', idx) gate
    int   tauI = 0x7fffffff;

    auto scan_range = [&](int s, int e) {
        for (int t = s; t < e; t += 32) {
            const int ti = t + lane;
            float d = FINF;
            int pid = 0;
            if (ti < e) {
                const float4 P = g_spts[ti];
                pid = g_sidx[ti];
                d = fmaf(nqx, P.x, fmaf(nqy, P.y, fmaf(nqz, P.z, P.w)));
            }
            const bool pass = (d < tau) || (d == tau && pid < tauI);
            unsigned bal = __ballot_sync(FULLMASK, pass);
            if (bal) {                          // warp-uniform
                do {
                    const int src = __ffs(bal) - 1;
                    bal &= bal - 1;
                    const float dc = __shfl_sync(FULLMASK, d, src);
                    const int   ic = __shfl_sync(FULLMASK, pid, src);
                    const unsigned mlt =
                        __ballot_sync(FULLMASK, (topd < dc) || (topd == dc && topi < ic)) & 0xFFFFu;
                    const int rank = __popc(mlt);
                    const float pd = __shfl_up_sync(FULLMASK, topd, 1);
                    const int   pi = __shfl_up_sync(FULLMASK, topi, 1);
                    if (lane < 16) {
                        if (lane == rank)     { topd = dc; topi = ic; }
                        else if (lane > rank) { topd = pd; topi = pi; }
                    }
                } while (bal);
                tau  = __shfl_sync(FULLMASK, topd, 15);
                tauI = __shfl_sync(FULLMASK, topi, 15);
            }
        }
    };

    for (int r = 1; r <= GD; r++) {
        for (int dz = -r; dz <= r; dz++) {
            const int z = cz + dz;
            if ((unsigned)z >= GD) continue;
            for (int dy = -r; dy <= r; dy++) {
                const int y = cy + dy;
                if ((unsigned)y >= GD) continue;
                const bool edge = (r == 1) || (dz == -r || dz == r || dy == -r || dy == r);
                const int rowb = cbase + (z * GD + y) * GD;
                if (edge) {
                    const int xa = max(cx - r, 0), xb = min(cx + r, GD - 1);
                    scan_range(g_cellstart[rowb + xa], g_cellstart[rowb + xb + 1]);
                } else {
                    const int xl = cx - r, xr = cx + r;
                    if (xl >= 0) scan_range(g_cellstart[rowb + xl], g_cellstart[rowb + xl + 1]);
                    if (xr < GD) scan_range(g_cellstart[rowb + xr], g_cellstart[rowb + xr + 1]);
                }
            }
        }
        if (tau < BIGF) {
            // lower bound on distance from q to anything outside box(r)
            float bmin = FINF;
            if (cx - r > 0)      bmin = fminf(bmin, qx - (LO + (cx - r) * HH));
            if (cx + r < GD - 1) bmin = fminf(bmin, (LO + (cx + r + 1) * HH) - qx);
            if (cy - r > 0)      bmin = fminf(bmin, qy - (LO + (cy - r) * HH));
            if (cy + r < GD - 1) bmin = fminf(bmin, (LO + (cy + r + 1) * HH) - qy);
            if (cz - r > 0)      bmin = fminf(bmin, qz - (LO + (cz - r) * HH));
            if (cz + r < GD - 1) bmin = fminf(bmin, (LO + (cz + r + 1) * HH) - qz);
            bmin = fmaxf(bmin, 0.0f);
            const float td2 = tau + qq;   // real squared distance of 16th
            if (bmin * bmin >= td2 + 1e-5f + 4e-6f * fabsf(td2)) break;
        }
    }

    // --- fused gather/mean: lanes 0..15 hold the top-16 (original indices) ---
    const float* ft = g_xt + (size_t)b * NN * CC;
    float a0 = 0.0f, a1 = 0.0f;
#pragma unroll
    for (int r = 0; r < KK; r++) {
        const int g = __shfl_sync(FULLMASK, topi, r);
        const float* f = ft + (size_t)g * CC;
        a0 += f[lane];
        a1 += f[lane + 32];
    }

    out[((size_t)b * CC + lane) * MM + m]      = a0 * (1.0f / KK);
    out[((size_t)b * CC + lane + 32) * MM + m] = a1 * (1.0f / KK);
}

// ---------------------------------------------------------------------------
extern "C" void kernel_launch(void* const* d_in, const int* in_sizes, int n_in,
                              void* d_out, int out_size) {
    const float* p1 = (const float*)d_in[0];   // (B, N, 3)
    const float* x1 = (const float*)d_in[1];   // (B, C, N)
    const float* p2 = (const float*)d_in[2];   // (B, M, 3)
    float* out = (float*)d_out;                // (B, C, M)

    zero_kernel<<<(NCTOT + 255) / 256, 256>>>();
    count_kernel<<<(BB * NN) / 256, 256>>>(p1);
    scan1_kernel<<<NSB, 1024>>>();
    scan2_kernel<<<1, 32>>>();
    scan3_kernel<<<(NCTOT + 255) / 256, 256>>>();
    scatter_kernel<<<(BB * NN) / 256, 256>>>(p1);

    dim3 tb(32, 8);
    dim3 tg(NN / 32, CC / 32, BB);
    transpose_kernel<<<tg, tb>>>(x1);

    knn_kernel<<<NQ / WPB, 32 * WPB>>>(p2, out);
}

// round 10
// speedup vs baseline: 2.1476x; 2.1476x over previous
#include <cuda_runtime.h>

// Problem constants (fixed shapes from reference)
#define BB   2
#define NN   16384
#define MM   4096
#define CC   64
#define KK   16
#define TILE 2048
#define HALF (NN / 2)     // points per split-K half
#define WPB  8            // warps per block
#define NQ   (BB * MM)    // 8192 total queries
#define NP   (NQ / 2)     // 4096 query-pairs

#define BIGF 1e30f
#define FULLMASK 0xffffffffu

// Scratch (__device__ globals; no allocs allowed)
__device__ float  g_xt[BB * NN * CC];   // transposed features (B,N,C), 8 MB
__device__ float4 g_pts[BB * NN];       // packed points (x,y,z,|p|^2)
__device__ float  g_pd[(size_t)NQ * 32];  // partial top-16 dists (2 halves x 16)
__device__ int    g_pi[(size_t)NQ * 32];  // partial top-16 indices

// ---------------------------------------------------------------------------
// Kernel 0: pack p1 (B,N,3) -> float4 (x, y, z, |p|^2)
// ---------------------------------------------------------------------------
__global__ __launch_bounds__(256) void pack_kernel(const float* __restrict__ p1) {
    const int i = blockIdx.x * 256 + threadIdx.x;  // 0 .. BB*NN-1
    const float x = p1[i * 3 + 0];
    const float y = p1[i * 3 + 1];
    const float z = p1[i * 3 + 2];
    g_pts[i] = make_float4(x, y, z, fmaf(x, x, fmaf(y, y, z * z)));
}

// ---------------------------------------------------------------------------
// Kernel 1: transpose x1 (B,C,N) -> g_xt (B,N,C) so neighbor gathers coalesce.
// ---------------------------------------------------------------------------
__global__ __launch_bounds__(256) void transpose_kernel(const float* __restrict__ x1) {
    __shared__ float t[32][33];
    const int b  = blockIdx.z;
    const int n0 = blockIdx.x * 32;
    const int c0 = blockIdx.y * 32;
    const int tx = threadIdx.x;
    const int ty = threadIdx.y;

    const float* src = x1  + (size_t)b * CC * NN;
    float*       dst = g_xt + (size_t)b * NN * CC;

#pragma unroll
    for (int i = 0; i < 32; i += 8)
        t[ty + i][tx] = src[(size_t)(c0 + ty + i) * NN + (n0 + tx)];
    __syncthreads();
#pragma unroll
    for (int i = 0; i < 32; i += 8)
        dst[(size_t)(n0 + ty + i) * CC + (c0 + tx)] = t[tx][ty + i];
}

// ---------------------------------------------------------------------------
// Kernel 2 (main): warp-distributed exact KNN(16) over HALF the points for
// TWO queries per warp. Lanes 0..15 hold q0's sorted top-16, lanes 16..31
// q1's. Split-K: blocks 0..511 scan points [0,8192), blocks 512..1023 scan
// [8192,16384) -> 2x the warps of R8 for latency hiding at identical total
// eval / smem-traffic cost. Hot path per 64 points: 2 LDS.128 + 12 FFMA +
// 2 FMIN + 2 ballots (gate on min of the two chunk distances; handler
// re-ballots per chunk exactly). d' = |p|^2 - 2 q.p (order-equiv).
// ---------------------------------------------------------------------------
__global__ __launch_bounds__(32 * WPB) void knn_main_kernel(const float* __restrict__ p2) {
    __shared__ float4 sp[TILE];   // 32 KB

    const int warp = threadIdx.x >> 5;
    const int lane = threadIdx.x & 31;
    const int h    = blockIdx.x >> 9;                       // half: 0 or 1
    const int P    = (blockIdx.x & 511) * WPB + warp;       // 0..NP-1
    const int b    = P >> 11;
    const int m0   = (P & 2047) * 2;

    const float* qp = p2 + ((size_t)b * MM + m0) * 3;
    const float n0x = -2.0f * qp[0], n0y = -2.0f * qp[1], n0z = -2.0f * qp[2];
    const float n1x = -2.0f * qp[3], n1y = -2.0f * qp[4], n1z = -2.0f * qp[5];

    const float4* gp = g_pts + (size_t)b * NN;

    float topd = BIGF;      // sorted top-16: q0 in lanes 0..15, q1 in 16..31
    int   topi = 0;
    float tau0 = BIGF;
    float tau1 = BIGF;

    auto insert0 = [&](float d, int idxbase) {
        unsigned bal = __ballot_sync(FULLMASK, d < tau0);
        if (bal) {
            do {
                const int src = __ffs(bal) - 1;
                bal &= bal - 1;
                const float dc = __shfl_sync(FULLMASK, d, src);
                const int   ic = idxbase + src;
                const int rank = __popc(__ballot_sync(FULLMASK, topd < dc) & 0xFFFFu);
                const float pd = __shfl_up_sync(FULLMASK, topd, 1);
                const int   pi = __shfl_up_sync(FULLMASK, topi, 1);
                if (lane < 16) {
                    if (lane == rank)     { topd = dc; topi = ic; }
                    else if (lane > rank) { topd = pd; topi = pi; }
                }
            } while (bal);
            tau0 = __shfl_sync(FULLMASK, topd, 15);
        }
    };
    auto insert1 = [&](float d, int idxbase) {
        unsigned bal = __ballot_sync(FULLMASK, d < tau1);
        if (bal) {
            do {
                const int src = __ffs(bal) - 1;
                bal &= bal - 1;
                const float dc = __shfl_sync(FULLMASK, d, src);
                const int   ic = idxbase + src;
                const int rank = 16 + __popc(__ballot_sync(FULLMASK, topd < dc) >> 16);
                const float pd = __shfl_up_sync(FULLMASK, topd, 1);
                const int   pi = __shfl_up_sync(FULLMASK, topi, 1);
                if (lane >= 16) {
                    if (lane == rank)     { topd = dc; topi = ic; }
                    else if (lane > rank) { topd = pd; topi = pi; }
                }
            } while (bal);
            tau1 = __shfl_sync(FULLMASK, topd, 31);
        }
    };

    const int hbeg = h * HALF;
    for (int t0 = hbeg; t0 < hbeg + HALF; t0 += TILE) {
        __syncthreads();
        for (int i = threadIdx.x; i < TILE; i += 32 * WPB)
            sp[i] = gp[t0 + i];
        __syncthreads();

#pragma unroll 4
        for (int j = 0; j < TILE / 32; j += 2) {
            const float4 Pa = sp[j * 32 + lane];
            const float4 Pb = sp[j * 32 + 32 + lane];
            const float d0a = fmaf(n0x, Pa.x, fmaf(n0y, Pa.y, fmaf(n0z, Pa.z, Pa.w)));
            const float d0b = fmaf(n0x, Pb.x, fmaf(n0y, Pb.y, fmaf(n0z, Pb.z, Pb.w)));
            const float d1a = fmaf(n1x, Pa.x, fmaf(n1y, Pa.y, fmaf(n1z, Pa.z, Pa.w)));
            const float d1b = fmaf(n1x, Pb.x, fmaf(n1y, Pb.y, fmaf(n1z, Pb.z, Pb.w)));
            const unsigned b0 = __ballot_sync(FULLMASK, fminf(d0a, d0b) < tau0);
            const unsigned b1 = __ballot_sync(FULLMASK, fminf(d1a, d1b) < tau1);
            if (b0 | b1) {                       // warp-uniform
                const int base = t0 + j * 32;
                if (b0) { insert0(d0a, base); insert0(d0b, base + 32); }
                if (b1) { insert1(d1a, base); insert1(d1b, base + 32); }
            }
        }
    }

    // --- write partial sorted lists: query Q, half h, slots 0..15 ---
    const int Q0 = b * MM + m0;        // global query id of q0 (q1 = Q0+1)
    if (lane < 16) {
        const size_t o = (size_t)Q0 * 32 + h * 16 + lane;
        g_pd[o] = topd;
        g_pi[o] = topi;
    } else {
        const size_t o = (size_t)(Q0 + 1) * 32 + h * 16 + (lane - 16);
        g_pd[o] = topd;
        g_pi[o] = topi;
    }
}

// ---------------------------------------------------------------------------
// Kernel 3: merge the two partial top-16 lists per query (disjoint index
// ranges -> all 32 (d,idx) distinct; tie-stable lexicographic compare) and
// do the fused feature gather/mean. One warp per query.
// ---------------------------------------------------------------------------
__global__ __launch_bounds__(32 * WPB) void merge_kernel(float* __restrict__ out) {
    const int warp = threadIdx.x >> 5;
    const int lane = threadIdx.x & 31;
    const int q    = blockIdx.x * WPB + warp;   // 0..NQ-1
    const int b    = q >> 12;
    const int m    = q & (MM - 1);

    float dv = g_pd[(size_t)q * 32 + lane];
    int   iv = g_pi[(size_t)q * 32 + lane];

    const float* ft = g_xt + (size_t)b * NN * CC;
    float a0 = 0.0f, a1 = 0.0f;
    const float FINF = __int_as_float(0x7f800000);

#pragma unroll 1
    for (int r = 0; r < KK; r++) {
        // warp argmin by (d, idx) — result is warp-uniform
        float v  = dv;
        int   i  = iv;
        int   ln = lane;
#pragma unroll
        for (int off = 16; off; off >>= 1) {
            const float ov = __shfl_xor_sync(FULLMASK, v, off);
            const int   oi = __shfl_xor_sync(FULLMASK, i, off);
            const int   ol = __shfl_xor_sync(FULLMASK, ln, off);
            if (ov < v || (ov == v && oi < i)) { v = ov; i = oi; ln = ol; }
        }
        if (lane == ln) { dv = FINF; iv = 0x7fffffff; }   // consume winner
        const float* f = ft + (size_t)i * CC;
        a0 += f[lane];
        a1 += f[lane + 32];
    }

    out[((size_t)b * CC + lane) * MM + m]      = a0 * (1.0f / KK);
    out[((size_t)b * CC + lane + 32) * MM + m] = a1 * (1.0f / KK);
}

// ---------------------------------------------------------------------------
extern "C" void kernel_launch(void* const* d_in, const int* in_sizes, int n_in,
                              void* d_out, int out_size) {
    const float* p1 = (const float*)d_in[0];   // (B, N, 3)
    const float* x1 = (const float*)d_in[1];   // (B, C, N)
    const float* p2 = (const float*)d_in[2];   // (B, M, 3)
    float* out = (float*)d_out;                // (B, C, M)

    pack_kernel<<<(BB * NN) / 256, 256>>>(p1);

    dim3 tb(32, 8);
    dim3 tg(NN / 32, CC / 32, BB);
    transpose_kernel<<<tg, tb>>>(x1);

    knn_main_kernel<<<2 * (NP / WPB), 32 * WPB>>>(p2);   // 1024 blocks
    merge_kernel<<<NQ / WPB, 32 * WPB>>>(out);
}

// round 12
// speedup vs baseline: 2.2197x; 1.0336x over previous
#include <cuda_runtime.h>
#include <math.h>

// Problem constants (fixed shapes from reference)
#define BB   2
#define NN   16384
#define MM   4096
#define CC   64
#define KK   16
#define NQ   (BB * MM)

#define NBIN   1024
#define BINLO  (-5.0f)
#define BINW   0.009765625f     /* 10/1024 exact */
#define INVW   102.4f

#define BIGF 1e30f
#define FULLMASK 0xffffffffu

// Scratch (__device__ globals; no allocs allowed)
__device__ float  g_xt[BB * NN * CC];     // transposed features (B,N,C), 8 MB
__device__ float4 g_spts[BB * NN];        // x-sorted packed points (x,y,z,|p|^2)
__device__ int    g_sidx[BB * NN];        // original index per sorted point
__device__ int    g_binstart[BB * (NBIN + 1)];
__device__ int    g_qorder[BB * MM];      // query ids sorted by x-bin

__device__ __forceinline__ int bin_of(float x) {
    return min(NBIN - 1, max(0, (int)floorf((x - BINLO) * INVW)));
}

// ---------------------------------------------------------------------------
// Build: 4 blocks of 1024 threads.
//   blocks 0,1: sort batch-b points by x-bin (hist -> scan -> scatter)
//   blocks 2,3: sort batch-b query ids by x-bin
// Within-bin order is atomic-nondeterministic; the knn selection is made
// order-independent by exact (d, original-idx) tie-stable compares.
// ---------------------------------------------------------------------------
__global__ __launch_bounds__(1024) void build_kernel(const float* __restrict__ p1,
                                                     const float* __restrict__ p2) {
    __shared__ int hist[NBIN];
    __shared__ int wsum[32];

    const int tid  = threadIdx.x;
    const int lane = tid & 31, wid = tid >> 5;
    const int b    = blockIdx.x & 1;
    const bool qrole = (blockIdx.x >= 2);
    const float* src = qrole ? (p2 + (size_t)b * MM * 3) : (p1 + (size_t)b * NN * 3);
    const int n = qrole ? MM : NN;

    hist[tid] = 0;
    __syncthreads();
    for (int i = tid; i < n; i += 1024)
        atomicAdd(&hist[bin_of(src[3 * i])], 1);
    __syncthreads();

    // exclusive block scan over hist[1024]
    const int v = hist[tid];
    int x = v;
#pragma unroll
    for (int o = 1; o < 32; o <<= 1) {
        const int t = __shfl_up_sync(FULLMASK, x, o);
        if (lane >= o) x += t;
    }
    if (lane == 31) wsum[wid] = x;
    __syncthreads();
    if (wid == 0) {
        const int wv = wsum[lane];
        int s = wv;
#pragma unroll
        for (int o = 1; o < 32; o <<= 1) {
            const int t = __shfl_up_sync(FULLMASK, s, o);
            if (lane >= o) s += t;
        }
        wsum[lane] = s - wv;
    }
    __syncthreads();
    const int excl = x - v + wsum[wid];
    __syncthreads();               // done reading hist as counts
    hist[tid] = excl;              // reuse as scatter cursor
    if (!qrole) {
        g_binstart[b * (NBIN + 1) + tid] = excl;
        if (tid == 0) g_binstart[b * (NBIN + 1) + NBIN] = NN;
    }
    __syncthreads();

    for (int i = tid; i < n; i += 1024) {
        const float xx = src[3 * i];
        const int pos = atomicAdd(&hist[bin_of(xx)], 1);
        if (qrole) {
            g_qorder[b * MM + pos] = i;
        } else {
            const float yy = src[3 * i + 1];
            const float zz = src[3 * i + 2];
            g_spts[b * NN + pos] = make_float4(xx, yy, zz, fmaf(xx, xx, fmaf(yy, yy, zz * zz)));
            g_sidx[b * NN + pos] = i;
        }
    }
}

// ---------------------------------------------------------------------------
// Feature transpose x1 (B,C,N) -> g_xt (B,N,C)
// ---------------------------------------------------------------------------
__global__ __launch_bounds__(256) void transpose_kernel(const float* __restrict__ x1) {
    __shared__ float t[32][33];
    const int b  = blockIdx.z;
    const int n0 = blockIdx.x * 32;
    const int c0 = blockIdx.y * 32;
    const int tx = threadIdx.x;
    const int ty = threadIdx.y;

    const float* src = x1  + (size_t)b * CC * NN;
    float*       dst = g_xt + (size_t)b * NN * CC;

#pragma unroll
    for (int i = 0; i < 32; i += 8)
        t[ty + i][tx] = src[(size_t)(c0 + ty + i) * NN + (n0 + tx)];
    __syncthreads();
#pragma unroll
    for (int i = 0; i < 32; i += 8)
        dst[(size_t)(n0 + ty + i) * CC + (c0 + tx)] = t[tx][ty + i];
}

// ---------------------------------------------------------------------------
// KNN: one warp = two x-adjacent queries (paired via g_qorder). Lanes 0..15
// hold q0's global top-16 sorted ascending by (d', idx); lanes 16..31 q1's.
// Scan a contiguous x-window of the sorted points with the R8 ballot hot
// loop; expand the window (warp-uniform) until the exact boundary bound
// (gap^2 >= d16^2 + margin) holds on both sides. Conservative gate d<=tau;
// insert handler is exact and tie-stable -> independent of scatter order.
// d' = |p|^2 - 2 q.p  (order-equivalent to |p-q|^2; d16^2 = tau + |q|^2).
// ---------------------------------------------------------------------------
__global__ __launch_bounds__(256) void knn_kernel(const float* __restrict__ p2,
                                                  float* __restrict__ out) {
    const int warp = threadIdx.x >> 5;
    const int lane = threadIdx.x & 31;
    const int W    = blockIdx.x * 8 + warp;   // 0..NQ/2-1
    const int b    = W >> 11;                 // W / (MM/2)
    const int slot = W & 2047;

    const int m0 = g_qorder[b * MM + 2 * slot];
    const int m1 = g_qorder[b * MM + 2 * slot + 1];

    const float* q0p = p2 + ((size_t)b * MM + m0) * 3;
    const float* q1p = p2 + ((size_t)b * MM + m1) * 3;
    const float qx0 = q0p[0], qy0 = q0p[1], qz0 = q0p[2];
    const float qx1 = q1p[0], qy1 = q1p[1], qz1 = q1p[2];
    const float n0x = -2.0f * qx0, n0y = -2.0f * qy0, n0z = -2.0f * qz0;
    const float n1x = -2.0f * qx1, n1y = -2.0f * qy1, n1z = -2.0f * qz1;
    const float qq0 = fmaf(qx0, qx0, fmaf(qy0, qy0, qz0 * qz0));
    const float qq1 = fmaf(qx1, qx1, fmaf(qy1, qy1, qz1 * qz1));

    const int pb  = b * NN;
    const int bsb = b * (NBIN + 1);
    const float FINF = __int_as_float(0x7f800000);

    float topd = BIGF;          // sorted lists: q0 lanes 0..15, q1 lanes 16..31
    int   topi = 0x7fffffff;
    float tau0 = BIGF, tau1 = BIGF;

    auto ins0 = [&](float dc, int ic) {
        const unsigned mlt =
            __ballot_sync(FULLMASK, (topd < dc) || (topd == dc && topi < ic)) & 0xFFFFu;
        const int rank = __popc(mlt);
        const float pd = __shfl_up_sync(FULLMASK, topd, 1);
        const int   pi = __shfl_up_sync(FULLMASK, topi, 1);
        if (lane < 16) {
            if (lane == rank)     { topd = dc; topi = ic; }
            else if (lane > rank) { topd = pd; topi = pi; }
        }
    };
    auto ins1 = [&](float dc, int ic) {
        const int rank = 16 + __popc(
            __ballot_sync(FULLMASK, (topd < dc) || (topd == dc && topi < ic)) >> 16);
        const float pd = __shfl_up_sync(FULLMASK, topd, 1);
        const int   pi = __shfl_up_sync(FULLMASK, topi, 1);
        if (lane >= 16) {
            if (lane == rank)     { topd = dc; topi = ic; }
            else if (lane > rank) { topd = pd; topi = pi; }
        }
    };

    auto scan_range = [&](int s, int e) {
        for (int t = s; t < e; t += 64) {
            const int t1 = t + lane, t2 = t + 32 + lane;
            float d0a = FINF, d1a = FINF, d0b = FINF, d1b = FINF;
            if (t1 < e) {
                const float4 P = g_spts[pb + t1];
                d0a = fmaf(n0x, P.x, fmaf(n0y, P.y, fmaf(n0z, P.z, P.w)));
                d1a = fmaf(n1x, P.x, fmaf(n1y, P.y, fmaf(n1z, P.z, P.w)));
            }
            if (t2 < e) {
                const float4 P = g_spts[pb + t2];
                d0b = fmaf(n0x, P.x, fmaf(n0y, P.y, fmaf(n0z, P.z, P.w)));
                d1b = fmaf(n1x, P.x, fmaf(n1y, P.y, fmaf(n1z, P.z, P.w)));
            }
            const unsigned g0 = __ballot_sync(FULLMASK, fminf(d0a, d0b) <= tau0);
            const unsigned g1 = __ballot_sync(FULLMASK, fminf(d1a, d1b) <= tau1);
            if (g0 | g1) {                            // warp-uniform
                const int pa = (t1 < e) ? g_sidx[pb + t1] : 0x7fffffff;
                const int pc = (t2 < e) ? g_sidx[pb + t2] : 0x7fffffff;
                if (g0) {
                    unsigned ba = __ballot_sync(FULLMASK, d0a <= tau0);
                    while (ba) {
                        const int s2 = __ffs(ba) - 1; ba &= ba - 1;
                        ins0(__shfl_sync(FULLMASK, d0a, s2), __shfl_sync(FULLMASK, pa, s2));
                    }
                    unsigned bc = __ballot_sync(FULLMASK, d0b <= tau0);
                    while (bc) {
                        const int s2 = __ffs(bc) - 1; bc &= bc - 1;
                        ins0(__shfl_sync(FULLMASK, d0b, s2), __shfl_sync(FULLMASK, pc, s2));
                    }
                    tau0 = __shfl_sync(FULLMASK, topd, 15);
                }
                if (g1) {
                    unsigned ba = __ballot_sync(FULLMASK, d1a <= tau1);
                    while (ba) {
                        const int s2 = __ffs(ba) - 1; ba &= ba - 1;
                        ins1(__shfl_sync(FULLMASK, d1a, s2), __shfl_sync(FULLMASK, pa, s2));
                    }
                    unsigned bc = __ballot_sync(FULLMASK, d1b <= tau1);
                    while (bc) {
                        const int s2 = __ffs(bc) - 1; bc &= bc - 1;
                        ins1(__shfl_sync(FULLMASK, d1b, s2), __shfl_sync(FULLMASK, pc, s2));
                    }
                    tau1 = __shfl_sync(FULLMASK, topd, 31);
                }
            }
        }
    };

    // initial window: bins spanning both queries, +-2
    const int qb0 = bin_of(qx0), qb1 = bin_of(qx1);
    int a   = max(min(qb0, qb1) - 2, 0);
    int bhi = min(max(qb0, qb1) + 2, NBIN - 1);
    int lo = g_binstart[bsb + a];
    int hi = g_binstart[bsb + bhi + 1];

    scan_range(lo, hi);

    for (;;) {
        const float t20 = tau0 + qq0;           // real squared 16th distances
        const float t21 = tau1 + qq1;
        const float l0 = t20 + 1e-5f + 4e-6f * fabsf(t20);
        const float l1 = t21 + 1e-5f + 4e-6f * fabsf(t21);
        const float xl = BINLO + a * BINW + 1e-4f;            // conservative edges
        const float xr = BINLO + (bhi + 1) * BINW - 1e-4f;
        const float gl0 = qx0 - xl, gl1 = qx1 - xl;
        const float gr0 = xr - qx0, gr1 = xr - qx1;
        const bool needL = (a > 0)        && (gl0 * gl0 < l0 || gl1 * gl1 < l1);
        const bool needR = (bhi < NBIN-1) && (gr0 * gr0 < l0 || gr1 * gr1 < l1);
        if (!needL && !needR) break;
        if (needL) {
            int na = a, nlo = lo;
            do { na = max(na - 4, 0); nlo = g_binstart[bsb + na]; }
            while (na > 0 && lo - nlo < 64);
            scan_range(nlo, lo);
            a = na; lo = nlo;
        }
        if (needR) {
            int nb = bhi, nhi = hi;
            do { nb = min(nb + 4, NBIN - 1); nhi = g_binstart[bsb + nb + 1]; }
            while (nb < NBIN - 1 && nhi - hi < 64);
            scan_range(hi, nhi);
            bhi = nb; hi = nhi;
        }
    }

    // --- fused gather/mean for both queries (original indices in topi) ---
    const float* ft = g_xt + (size_t)b * NN * CC;
    float a0 = 0.0f, a1 = 0.0f;   // q0: channels [lane], [lane+32]
    float c0 = 0.0f, c1 = 0.0f;   // q1
#pragma unroll
    for (int r = 0; r < KK; r++) {
        const int gA = __shfl_sync(FULLMASK, topi, r);
        const int gB = __shfl_sync(FULLMASK, topi, 16 + r);
        const float* fA = ft + (size_t)gA * CC;
        const float* fB = ft + (size_t)gB * CC;
        a0 += fA[lane];
        a1 += fA[lane + 32];
        c0 += fB[lane];
        c1 += fB[lane + 32];
    }

    out[((size_t)b * CC + lane) * MM + m0]        = a0 * (1.0f / KK);
    out[((size_t)b * CC + lane + 32) * MM + m0]   = a1 * (1.0f / KK);
    out[((size_t)b * CC + lane) * MM + m1]        = c0 * (1.0f / KK);
    out[((size_t)b * CC + lane + 32) * MM + m1]   = c1 * (1.0f / KK);
}

// ---------------------------------------------------------------------------
extern "C" void kernel_launch(void* const* d_in, const int* in_sizes, int n_in,
                              void* d_out, int out_size) {
    const float* p1 = (const float*)d_in[0];   // (B, N, 3)
    const float* x1 = (const float*)d_in[1];   // (B, C, N)
    const float* p2 = (const float*)d_in[2];   // (B, M, 3)
    float* out = (float*)d_out;                // (B, C, M)

    build_kernel<<<4, 1024>>>(p1, p2);

    dim3 tb(32, 8);
    dim3 tg(NN / 32, CC / 32, BB);
    transpose_kernel<<<tg, tb>>>(x1);

    knn_kernel<<<NQ / 2 / 8, 256>>>(p2, out);
}

// round 14
// speedup vs baseline: 2.4601x; 1.1083x over previous
#include <cuda_runtime.h>
#include <math.h>

// Problem constants (fixed shapes from reference)
#define BB   2
#define NN   16384
#define MM   4096
#define CC   64
#define KK   16
#define NQ   (BB * MM)
#define TILE 2048
#define QPB  16            // queries per block
#define TPB  256           // threads per block (8 warps x 2 queries)

#define NBIN  1024
#define BINLO (-5.0f)
#define BINW  0.009765625f  /* 10/1024, exact in fp32 */
#define INVW  102.4f
#define R0    0.30f         /* initial slab half-width */
#define STEPB 8             /* expansion step in bins */

#define BIGF 1e30f
#define FULLMASK 0xffffffffu

// Scratch (__device__ globals; no allocs allowed)
__device__ float  g_xt[BB * NN * CC];      // transposed features (B,N,C)
__device__ float4 g_spts[BB * NN];         // x-sorted points (x,y,z,(float)orig_idx)
__device__ int    g_pstart[BB * (NBIN + 1)];
__device__ int    g_pcnt[BB * NBIN];
__device__ int    g_pcur[BB * NBIN];
__device__ int    g_qcnt[BB * NBIN];
__device__ int    g_qcur[BB * NBIN];
__device__ int    g_qorder[BB * MM];       // query ids sorted by x-bin

__device__ __forceinline__ int bin_of(float x) {
    return min(NBIN - 1, max(0, (int)floorf((x - BINLO) * INVW)));
}

// ---------------------------------------------------------------------------
// Build kernels (wide grids; ~6-8us total)
// ---------------------------------------------------------------------------
__global__ __launch_bounds__(256) void zero_kernel() {
    const int i = blockIdx.x * 256 + threadIdx.x;
    if (i < BB * NBIN) { g_pcnt[i] = 0; g_qcnt[i] = 0; }
}

__global__ __launch_bounds__(256) void count_kernel(const float* __restrict__ p1,
                                                    const float* __restrict__ p2) {
    if (blockIdx.x < 128) {
        const int i = blockIdx.x * 256 + threadIdx.x;          // 0..BB*NN-1
        atomicAdd(&g_pcnt[(i >> 14) * NBIN + bin_of(p1[3 * i])], 1);
    } else {
        const int i = (blockIdx.x - 128) * 256 + threadIdx.x;  // 0..BB*MM-1
        atomicAdd(&g_qcnt[(i >> 12) * NBIN + bin_of(p2[3 * i])], 1);
    }
}

__global__ __launch_bounds__(1024) void scan_kernel() {
    __shared__ int wsum[32];
    const int tid = threadIdx.x, lane = tid & 31, wid = tid >> 5;
    const int b = blockIdx.x & 1;
    const bool qrole = (blockIdx.x >= 2);
    const int v = qrole ? g_qcnt[b * NBIN + tid] : g_pcnt[b * NBIN + tid];
    int x = v;
#pragma unroll
    for (int o = 1; o < 32; o <<= 1) {
        const int t = __shfl_up_sync(FULLMASK, x, o);
        if (lane >= o) x += t;
    }
    if (lane == 31) wsum[wid] = x;
    __syncthreads();
    if (wid == 0) {
        const int wv = wsum[lane];
        int s = wv;
#pragma unroll
        for (int o = 1; o < 32; o <<= 1) {
            const int t = __shfl_up_sync(FULLMASK, s, o);
            if (lane >= o) s += t;
        }
        wsum[lane] = s - wv;
    }
    __syncthreads();
    const int excl = x - v + wsum[wid];
    if (qrole) {
        g_qcur[b * NBIN + tid] = excl;
    } else {
        g_pcur[b * NBIN + tid] = excl;
        g_pstart[b * (NBIN + 1) + tid] = excl;
        if (tid == 0) g_pstart[b * (NBIN + 1) + NBIN] = NN;
    }
}

__global__ __launch_bounds__(256) void scatter_kernel(const float* __restrict__ p1,
                                                      const float* __restrict__ p2) {
    if (blockIdx.x < 128) {
        const int i = blockIdx.x * 256 + threadIdx.x;
        const int b = i >> 14;
        const float x = p1[3 * i], y = p1[3 * i + 1], z = p1[3 * i + 2];
        const int pos = atomicAdd(&g_pcur[b * NBIN + bin_of(x)], 1);
        g_spts[b * NN + pos] = make_float4(x, y, z, (float)(i & (NN - 1)));
    } else {
        const int i = (blockIdx.x - 128) * 256 + threadIdx.x;
        const int b = i >> 12;
        const int pos = atomicAdd(&g_qcur[b * NBIN + bin_of(p2[3 * i])], 1);
        g_qorder[b * MM + pos] = i & (MM - 1);
    }
}

// ---------------------------------------------------------------------------
// Feature transpose x1 (B,C,N) -> g_xt (B,N,C)
// ---------------------------------------------------------------------------
__global__ __launch_bounds__(256) void transpose_kernel(const float* __restrict__ x1) {
    __shared__ float t[32][33];
    const int b  = blockIdx.z;
    const int n0 = blockIdx.x * 32;
    const int c0 = blockIdx.y * 32;
    const int tx = threadIdx.x;
    const int ty = threadIdx.y;

    const float* src = x1  + (size_t)b * CC * NN;
    float*       dst = g_xt + (size_t)b * NN * CC;

#pragma unroll
    for (int i = 0; i < 32; i += 8)
        t[ty + i][tx] = src[(size_t)(c0 + ty + i) * NN + (n0 + tx)];
    __syncthreads();
#pragma unroll
    for (int i = 0; i < 32; i += 8)
        dst[(size_t)(n0 + ty + i) * CC + (c0 + tx)] = t[tx][ty + i];
}

// ---------------------------------------------------------------------------
// KNN: block = 16 x-adjacent queries (8 warps x 2). The block scans ONE
// contiguous x-slab of the sorted points through smem tiles with the proven
// R8 ballot hot loop; then a block-uniform expansion loop extends the slab
// until every warp's exact boundary bound holds (conservative fp margins ->
// over-scan only, never a miss). Tie-stable (d', idx) selection makes the
// result independent of the nondeterministic within-bin scatter order.
// d' = |p|^2 - 2 q.p (order-equivalent); d16^2 = tau + |q|^2.
// ---------------------------------------------------------------------------
__global__ __launch_bounds__(TPB) void knn_kernel(const float* __restrict__ p2,
                                                  float* __restrict__ out) {
    __shared__ float4 sp[TILE];    // 32 KB
    __shared__ float  s_qx[QPB];

    const int tid  = threadIdx.x;
    const int warp = tid >> 5, lane = tid & 31;
    const int b     = blockIdx.x >> 8;            // 256 blocks per batch
    const int qbase = (blockIdx.x & 255) * QPB;

    const int m0 = g_qorder[b * MM + qbase + 2 * warp];
    const int m1 = g_qorder[b * MM + qbase + 2 * warp + 1];

    const float* q0p = p2 + ((size_t)b * MM + m0) * 3;
    const float* q1p = p2 + ((size_t)b * MM + m1) * 3;
    const float qx0 = q0p[0], qy0 = q0p[1], qz0 = q0p[2];
    const float qx1 = q1p[0], qy1 = q1p[1], qz1 = q1p[2];
    const float n0x = -2.0f * qx0, n0y = -2.0f * qy0, n0z = -2.0f * qz0;
    const float n1x = -2.0f * qx1, n1y = -2.0f * qy1, n1z = -2.0f * qz1;
    const float qq0 = fmaf(qx0, qx0, fmaf(qy0, qy0, qz0 * qz0));
    const float qq1 = fmaf(qx1, qx1, fmaf(qy1, qy1, qz1 * qz1));

    if (tid < QPB) {
        const int mq = g_qorder[b * MM + qbase + tid];
        s_qx[tid] = p2[((size_t)b * MM + mq) * 3];
    }
    __syncthreads();
    float xmn = s_qx[0], xmx = s_qx[0];
#pragma unroll
    for (int i = 1; i < QPB; i++) { xmn = fminf(xmn, s_qx[i]); xmx = fmaxf(xmx, s_qx[i]); }

    const float FINF = __int_as_float(0x7f800000);
    float topd = BIGF;           // sorted lists: q0 lanes 0..15, q1 lanes 16..31
    int   topi = 0x7fffffff;
    float tau0 = BIGF, tau1 = BIGF;

    auto ins0 = [&](float dc, int ic) {
        const unsigned mlt =
            __ballot_sync(FULLMASK, (topd < dc) || (topd == dc && topi < ic)) & 0xFFFFu;
        const int rank = __popc(mlt);
        const float pd = __shfl_up_sync(FULLMASK, topd, 1);
        const int   pi = __shfl_up_sync(FULLMASK, topi, 1);
        if (lane < 16) {
            if (lane == rank)     { topd = dc; topi = ic; }
            else if (lane > rank) { topd = pd; topi = pi; }
        }
    };
    auto ins1 = [&](float dc, int ic) {
        const int rank = 16 + __popc(
            __ballot_sync(FULLMASK, (topd < dc) || (topd == dc && topi < ic)) >> 16);
        const float pd = __shfl_up_sync(FULLMASK, topd, 1);
        const int   pi = __shfl_up_sync(FULLMASK, topi, 1);
        if (lane >= 16) {
            if (lane == rank)     { topd = dc; topi = ic; }
            else if (lane > rank) { topd = pd; topi = pi; }
        }
    };

#define KNN_CHUNK(J, CNT, GUARD)                                                 \
    {                                                                            \
        float d0a = FINF, d0b = FINF, d1a = FINF, d1b = FINF;                    \
        int ia = 0, ib = 0;                                                      \
        if (!(GUARD) || (J) + lane < (CNT)) {                                    \
            const float4 P = sp[(J) + lane];                                     \
            const float pp = fmaf(P.x, P.x, fmaf(P.y, P.y, P.z * P.z));          \
            d0a = fmaf(n0x, P.x, fmaf(n0y, P.y, fmaf(n0z, P.z, pp)));            \
            d1a = fmaf(n1x, P.x, fmaf(n1y, P.y, fmaf(n1z, P.z, pp)));            \
            ia = (int)P.w;                                                       \
        }                                                                        \
        if (!(GUARD) || (J) + 32 + lane < (CNT)) {                               \
            const float4 P = sp[(J) + 32 + lane];                                \
            const float pp = fmaf(P.x, P.x, fmaf(P.y, P.y, P.z * P.z));          \
            d0b = fmaf(n0x, P.x, fmaf(n0y, P.y, fmaf(n0z, P.z, pp)));            \
            d1b = fmaf(n1x, P.x, fmaf(n1y, P.y, fmaf(n1z, P.z, pp)));            \
            ib = (int)P.w;                                                       \
        }                                                                        \
        const unsigned g0 = __ballot_sync(FULLMASK, fminf(d0a, d0b) <= tau0);    \
        const unsigned g1 = __ballot_sync(FULLMASK, fminf(d1a, d1b) <= tau1);    \
        if (g0 | g1) {                                                           \
            if (g0) {                                                            \
                unsigned ba = __ballot_sync(FULLMASK, d0a <= tau0);              \
                while (ba) { const int s2 = __ffs(ba) - 1; ba &= ba - 1;         \
                    ins0(__shfl_sync(FULLMASK, d0a, s2),                         \
                         __shfl_sync(FULLMASK, ia, s2)); }                       \
                unsigned bc = __ballot_sync(FULLMASK, d0b <= tau0);              \
                while (bc) { const int s2 = __ffs(bc) - 1; bc &= bc - 1;         \
                    ins0(__shfl_sync(FULLMASK, d0b, s2),                         \
                         __shfl_sync(FULLMASK, ib, s2)); }                       \
                tau0 = __shfl_sync(FULLMASK, topd, 15);                          \
            }                                                                    \
            if (g1) {                                                            \
                unsigned ba = __ballot_sync(FULLMASK, d1a <= tau1);              \
                while (ba) { const int s2 = __ffs(ba) - 1; ba &= ba - 1;         \
                    ins1(__shfl_sync(FULLMASK, d1a, s2),                         \
                         __shfl_sync(FULLMASK, ia, s2)); }                       \
                unsigned bc = __ballot_sync(FULLMASK, d1b <= tau1);              \
                while (bc) { const int s2 = __ffs(bc) - 1; bc &= bc - 1;         \
                    ins1(__shfl_sync(FULLMASK, d1b, s2),                         \
                         __shfl_sync(FULLMASK, ib, s2)); }                       \
                tau1 = __shfl_sync(FULLMASK, topd, 31);                          \
            }                                                                    \
        }                                                                        \
    }

    // Block-cooperative tile scan over a contiguous sorted-point range.
    // Must be called with block-uniform (s, e).
    auto scan_pts = [&](int s, int e) {
        for (int t0 = s; t0 < e; t0 += TILE) {
            const int cnt = min(TILE, e - t0);
            __syncthreads();
            for (int i = tid; i < cnt; i += TPB)
                sp[i] = g_spts[b * NN + t0 + i];
            __syncthreads();
            if (cnt == TILE) {
                for (int j = 0; j < TILE; j += 64) KNN_CHUNK(j, TILE, false)
            } else {
                for (int j = 0; j < cnt; j += 64) KNN_CHUNK(j, cnt, true)
            }
        }
    };

    const int bsb = b * (NBIN + 1);
    int a  = bin_of(xmn - R0);
    int bh = bin_of(xmx + R0);
    int lo = g_pstart[bsb + a];
    int hi = g_pstart[bsb + bh + 1];

    scan_pts(lo, hi);

    // Block-uniform exact expansion loop
    for (;;) {
        const float t20 = tau0 + qq0;           // real squared 16th distances
        const float t21 = tau1 + qq1;
        const float l0 = t20 + 1e-5f + 4e-6f * fabsf(t20);
        const float l1 = t21 + 1e-5f + 4e-6f * fabsf(t21);
        const float xl = BINLO + a * BINW + 1e-4f;          // conservative edges
        const float xr = BINLO + (bh + 1) * BINW - 1e-4f;
        const float gl0 = qx0 - xl, gl1 = qx1 - xl;
        const float gr0 = xr - qx0, gr1 = xr - qx1;
        const bool needL = (a > 0) && (gl0 * gl0 < l0 || gl1 * gl1 < l1);
        const bool needR = (bh < NBIN - 1) && (gr0 * gr0 < l0 || gr1 * gr1 < l1);
        const int anyL = __syncthreads_or(needL ? 1 : 0);
        const int anyR = __syncthreads_or(needR ? 1 : 0);
        if (!(anyL | anyR)) break;
        if (anyL) {
            const int na  = max(a - STEPB, 0);
            const int nlo = g_pstart[bsb + na];
            scan_pts(nlo, lo);
            a = na; lo = nlo;
        }
        if (anyR) {
            const int nb  = min(bh + STEPB, NBIN - 1);
            const int nhi = g_pstart[bsb + nb + 1];
            scan_pts(hi, nhi);
            bh = nb; hi = nhi;
        }
    }
#undef KNN_CHUNK

    // --- fused gather/mean for both queries (original indices in topi) ---
    const float* ft = g_xt + (size_t)b * NN * CC;
    float a0 = 0.0f, a1 = 0.0f;   // q0: channels [lane], [lane+32]
    float c0 = 0.0f, c1 = 0.0f;   // q1
#pragma unroll
    for (int r = 0; r < KK; r++) {
        const int gA = __shfl_sync(FULLMASK, topi, r);
        const int gB = __shfl_sync(FULLMASK, topi, 16 + r);
        const float* fA = ft + (size_t)gA * CC;
        const float* fB = ft + (size_t)gB * CC;
        a0 += fA[lane];
        a1 += fA[lane + 32];
        c0 += fB[lane];
        c1 += fB[lane + 32];
    }

    out[((size_t)b * CC + lane) * MM + m0]        = a0 * (1.0f / KK);
    out[((size_t)b * CC + lane + 32) * MM + m0]   = a1 * (1.0f / KK);
    out[((size_t)b * CC + lane) * MM + m1]        = c0 * (1.0f / KK);
    out[((size_t)b * CC + lane + 32) * MM + m1]   = c1 * (1.0f / KK);
}

// ---------------------------------------------------------------------------
extern "C" void kernel_launch(void* const* d_in, const int* in_sizes, int n_in,
                              void* d_out, int out_size) {
    const float* p1 = (const float*)d_in[0];   // (B, N, 3)
    const float* x1 = (const float*)d_in[1];   // (B, C, N)
    const float* p2 = (const float*)d_in[2];   // (B, M, 3)
    float* out = (float*)d_out;                // (B, C, M)

    zero_kernel<<<8, 256>>>();
    count_kernel<<<160, 256>>>(p1, p2);
    scan_kernel<<<4, 1024>>>();
    scatter_kernel<<<160, 256>>>(p1, p2);

    dim3 tb(32, 8);
    dim3 tg(NN / 32, CC / 32, BB);
    transpose_kernel<<<tg, tb>>>(x1);

    knn_kernel<<<NQ / QPB, TPB>>>(p2, out);
}